// round 16
// baseline (speedup 1.0000x reference)
#include <cuda_runtime.h>
#include <cuda_bf16.h>
#include <math.h>

// Problem constants
#define BATCH   128
#define TSTEPS  256
#define BT      32768          // BATCH*TSTEPS
#define HCAT    1024           // 512+256+256

typedef unsigned int uint;

// ---------------- scratch (device globals; no allocation allowed) -------------
__device__ __nv_bfloat16 g_gx0b[(size_t)BT * 2048];  // layer0 input proj (i,f,g,o), bf16
__device__ __nv_bfloat16 g_gx1b[(size_t)BT * 1024];  // layer1
__device__ __nv_bfloat16 g_gx2b[(size_t)BT * 1024];  // layer2
__device__ float g_hcat[(size_t)BT * HCAT];  // hidden trajectories fp32, [b][t][1024]
__device__ float g_z[(size_t)BT * 256];      // FC1 output
__device__ __nv_bfloat16 g_hb[2][131072];    // recurrent h, bf16 mma-fragment layout, dbl buf
__device__ unsigned int g_flags[128];        // per-CTA barrier flags

__global__ void reset_kernel() { if (threadIdx.x < 128) g_flags[threadIdx.x] = 0u; }

// ------------------------------------------------------------------------------
// helpers
// ------------------------------------------------------------------------------
// bf16 m16n8k16 mma, fp32 accum
__device__ __forceinline__ void mma16(float (&d)[4], uint4 a, uint b0, uint b1) {
    asm volatile("mma.sync.aligned.m16n8k16.row.col.f32.bf16.bf16.f32 "
                 "{%0,%1,%2,%3}, {%4,%5,%6,%7}, {%8,%9}, {%0,%1,%2,%3};"
                 : "+f"(d[0]), "+f"(d[1]), "+f"(d[2]), "+f"(d[3])
                 : "r"(a.x), "r"(a.y), "r"(a.z), "r"(a.w), "r"(b0), "r"(b1));
}

__device__ __forceinline__ uint pack_bf16x2(float lo, float hi) {
    __nv_bfloat162 t = __floats2bfloat162_rn(lo, hi);
    return *(uint*)&t;
}

__device__ __forceinline__ float sigf(float x) { return 1.f / (1.f + __expf(-x)); }
__device__ __forceinline__ float tanhfast(float x) {
    const float e = __expf(-2.f * fabsf(x));
    const float r = (1.f - e) / (1.f + e);
    return copysignf(r, x);
}

__device__ __forceinline__ void cpa16(void* dst, const void* src, int srcbytes) {
    unsigned d = (unsigned)__cvta_generic_to_shared(dst);
    asm volatile("cp.async.ca.shared.global [%0], [%1], 16, %2;"
                 :: "r"(d), "l"(src), "r"(srcbytes));
}

// ------------------------------------------------------------------------------
// bf16 tensor-core GEMM: C[M,N] = A[M,K] @ W[N,K]^T + b1 (+b2) (+relu)
// BM=128, BN=64, BK=16; 256 threads = 8 warps (4m x 2n), warp tile 32x32.
// fp32 in smem; fragments packed to bf16x2 in registers (RN, zero-mean).
// Output: c_sel 0..2 -> bf16 gx buffers (halves the dominant write streams);
// c_sel 3 -> fp32 g_z.
// K%4==0 path: 3-stage cp.async pipeline, compute-then-issue, one sync/tile.
// ------------------------------------------------------------------------------
__device__ __forceinline__ void gemm_compute(
    const float (*As)[20], const float (*Ws)[20],
    float (&acc)[2][4][4], int wm, int wn, int g, int c)
{
    uint4 a[2]; uint b[4][2];
    #pragma unroll
    for (int mt = 0; mt < 2; mt++) {
        const int mr = wm * 32 + mt * 16 + g;
        a[mt].x = pack_bf16x2(As[mr    ][c * 2    ], As[mr    ][c * 2 + 1]);
        a[mt].y = pack_bf16x2(As[mr + 8][c * 2    ], As[mr + 8][c * 2 + 1]);
        a[mt].z = pack_bf16x2(As[mr    ][c * 2 + 8], As[mr    ][c * 2 + 9]);
        a[mt].w = pack_bf16x2(As[mr + 8][c * 2 + 8], As[mr + 8][c * 2 + 9]);
    }
    #pragma unroll
    for (int nt = 0; nt < 4; nt++) {
        const int nc = wn * 32 + nt * 8 + g;
        b[nt][0] = pack_bf16x2(Ws[nc][c * 2    ], Ws[nc][c * 2 + 1]);
        b[nt][1] = pack_bf16x2(Ws[nc][c * 2 + 8], Ws[nc][c * 2 + 9]);
    }
    #pragma unroll
    for (int mt = 0; mt < 2; mt++)
        #pragma unroll
        for (int nt = 0; nt < 4; nt++)
            mma16(acc[mt][nt], a[mt], b[nt][0], b[nt][1]);
}

__device__ __forceinline__ int clamp16(int bytes) {
    return bytes < 0 ? 0 : (bytes > 16 ? 16 : bytes);
}

__global__ __launch_bounds__(256, 2) void gemm_bf16(
    const float* __restrict__ Aext, int a_sel,
    const float* __restrict__ W,
    const float* __restrict__ b1, const float* __restrict__ b2,
    int c_sel, int M, int N, int K, int relu)
{
    __shared__ float As[3][128][20];
    __shared__ float Ws[3][64][20];

    const float* A = (a_sel == 0) ? g_hcat : Aext;
    __nv_bfloat16* Cb = nullptr;
    if      (c_sel == 0) Cb = g_gx0b;
    else if (c_sel == 1) Cb = g_gx1b;
    else if (c_sel == 2) Cb = g_gx2b;

    const int tid = threadIdx.x, lane = tid & 31, w = tid >> 5;
    const int wm = w >> 1, wn = w & 1;
    const int m0 = blockIdx.y * 128, n0 = blockIdx.x * 64;
    const int g = lane >> 2, c = lane & 3;

    float acc[2][4][4];
    #pragma unroll
    for (int mt = 0; mt < 2; mt++)
        #pragma unroll
        for (int nt = 0; nt < 4; nt++)
            #pragma unroll
            for (int e = 0; e < 4; e++) acc[mt][nt][e] = 0.f;

    const int ktiles = (K + 15) >> 4;

    if ((K & 3) == 0) {
        // ---- 3-stage cp.async pipeline ----
        const int arow = tid >> 1, akq = (tid & 1) * 8;       // A: 2 chunks/thread
        const int wrow = tid >> 2, wkq = (tid & 3) * 4;       // W: 1 chunk/thread

        auto issue_tile = [&](int kt) {
            const int kb = kt << 4;
            const int bf = kt % 3;
            const float* s0 = &A[(size_t)(m0 + arow) * K + kb + akq];
            const int r0 = clamp16((K - kb - akq) * 4);
            const int r1 = clamp16((K - kb - akq - 4) * 4);
            cpa16(&As[bf][arow][akq], r0 ? s0 : A, r0);
            cpa16(&As[bf][arow][akq + 4], r1 ? s0 + 4 : A, r1);
            const float* sw = &W[(size_t)(n0 + wrow) * K + kb + wkq];
            const int rw = clamp16((K - kb - wkq) * 4);
            cpa16(&Ws[bf][wrow][wkq], rw ? sw : W, rw);
            asm volatile("cp.async.commit_group;");
        };

        issue_tile(0);
        if (ktiles > 1) issue_tile(1);

        for (int kt = 0; kt < ktiles; kt++) {
            if (kt + 1 < ktiles) { asm volatile("cp.async.wait_group 1;"); }
            else                 { asm volatile("cp.async.wait_group 0;"); }
            __syncthreads();   // everyone's tile-kt copies visible; prior reads of
                               // buf (kt+2)%3 (= compute kt-1) are globally done
            gemm_compute(As[kt % 3], Ws[kt % 3], acc, wm, wn, g, c);
            if (kt + 2 < ktiles) issue_tile(kt + 2);
        }
    } else {
        // ---- generic path (small K: 74, 35) ----
        const int k = tid & 15, mi = tid >> 4;
        for (int kt = 0; kt < ktiles; kt++) {
            const int kb = kt << 4;
            #pragma unroll
            for (int p = 0; p < 8; p++) {
                const int m = mi + p * 16;
                As[0][m][k] = (kb + k < K) ? A[(size_t)(m0 + m) * K + kb + k] : 0.f;
            }
            #pragma unroll
            for (int p = 0; p < 4; p++) {
                const int n = mi + p * 16;
                Ws[0][n][k] = (kb + k < K) ? W[(size_t)(n0 + n) * K + kb + k] : 0.f;
            }
            __syncthreads();
            gemm_compute(As[0], Ws[0], acc, wm, wn, g, c);
            __syncthreads();
        }
    }

    #pragma unroll
    for (int mt = 0; mt < 2; mt++) {
        #pragma unroll
        for (int nt = 0; nt < 4; nt++) {
            const int nc = n0 + wn * 32 + nt * 8 + c * 2;
            float bb0 = b1[nc], bb1 = b1[nc + 1];
            if (b2) { bb0 += b2[nc]; bb1 += b2[nc + 1]; }
            #pragma unroll
            for (int hf = 0; hf < 2; hf++) {
                const int mr = m0 + wm * 32 + mt * 16 + g + hf * 8;
                float v0 = acc[mt][nt][hf * 2 + 0] + bb0;
                float v1 = acc[mt][nt][hf * 2 + 1] + bb1;
                if (relu) { v0 = fmaxf(v0, 0.f); v1 = fmaxf(v1, 0.f); }
                if (Cb) {
                    *(uint*)&Cb[(size_t)mr * N + nc] = pack_bf16x2(v0, v1);
                } else {
                    float2 st = make_float2(v0, v1);
                    *(float2*)&g_z[(size_t)mr * N + nc] = st;
                }
            }
        }
    }
}

// ------------------------------------------------------------------------------
// Recurrence bf16 mma inner loop; 4-deep register-ring prefetch (8 LDG.128).
// acc arrives pre-initialized with gx (mma accumulates on top).
// ------------------------------------------------------------------------------
template<int KG>
__device__ __forceinline__ void rec_mma(
    float (&acc)[2][2][4], const uint4* __restrict__ hbp,
    int tb0, int tb1, int lane,
    const uint* __restrict__ wsp, int wld, int g, int c)
{
    uint4 R0[4], R1[4];
    #pragma unroll
    for (int p = 0; p < 4; p++) {
        R0[p] = __ldcg(hbp + (tb0 + p) * 32 + lane);
        R1[p] = __ldcg(hbp + (tb1 + p) * 32 + lane);
    }
    #pragma unroll
    for (int kg = 0; kg < KG; kg++) {
        const int s = kg & 3;
        const uint4 a0 = R0[s], a1 = R1[s];
        if (kg + 4 < KG) {
            R0[s] = __ldcg(hbp + (tb0 + kg + 4) * 32 + lane);
            R1[s] = __ldcg(hbp + (tb1 + kg + 4) * 32 + lane);
        }
        #pragma unroll
        for (int nt = 0; nt < 2; nt++) {
            const uint b0 = wsp[(nt * 8 + g) * wld + kg * 8 + c];
            const uint b1 = wsp[(nt * 8 + g) * wld + kg * 8 + 4 + c];
            mma16(acc[0][nt], a0, b0, b1);
            mma16(acc[1][nt], a1, b0, b1);
        }
    }
}

// ------------------------------------------------------------------------------
// Persistent LSTM recurrence (bf16 tensor cores). 128 CTAs x 256 threads.
// CTA owns 4 cells of layer0 (unit A, warps 0-3) and 4 cells of layer1/2
// (unit B, warps 4-7).
// gx is loaded in mma-fragment domain (bf16x2 words) and initializes acc
// directly: column jj = nt*8+c*2 -> gate = nt*2+(c>>1), cell = (c&1)*2, so a
// thread's two acc columns are one aligned bf16x2 in gx. This removes the gx
// staging pass and one __syncthreads (3 syncs/step), and makes the gate-smem
// writes pure stores. Cell state in registers; release/acquire grid barrier;
// paired bf16x2 h-stores; gx(t+1) prefetched over the barrier wait.
// ------------------------------------------------------------------------------
__global__ void __launch_bounds__(256, 1) lstm_rec(
    const float* __restrict__ Whh0,
    const float* __restrict__ Whh1,
    const float* __restrict__ Whh2)
{
    extern __shared__ uint smu[];
    uint*  wsA = smu;                        // [16][260]  bf16x2 B-fragment words
    uint*  wsB = wsA + 16 * 260;             // [16][132]
    float* gsA = (float*)(wsB + 16 * 132);   // [16][132] gate preacts fp32
    float* gsB = gsA + 16 * 132;             // [16][132]
    float* hstage = gsB + 16 * 132;          // [8][132]  h values for coalesced hcat write

    const int cta = blockIdx.x, tid = threadIdx.x;
    const int lane = tid & 31, w = tid >> 5;
    const int cbA = cta * 4;

    const float* WB; const __nv_bfloat16* gxBb; int coloffB, cbB, lbB_elem, lbB_u4;
    if (cta < 64) { WB = Whh1; gxBb = g_gx1b; coloffB = 512; cbB = cta * 4;        lbB_elem = 65536; lbB_u4 = 8192; }
    else          { WB = Whh2; gxBb = g_gx2b; coloffB = 768; cbB = (cta - 64) * 4; lbB_elem = 98304; lbB_u4 = 12288; }

    // ---- one-time weight stage: pack bf16x2 B-fragment words ----
    for (int i = tid; i < 16 * 256; i += 256) {
        const int jj = i >> 8, ww = i & 255;
        const int kg = ww >> 3, sub = ww & 7;
        const int k = kg * 16 + (sub >> 2) * 8 + (sub & 3) * 2;
        const float* row = &Whh0[(size_t)((jj >> 2) * 512 + cbA + (jj & 3)) * 512];
        wsA[jj * 260 + ww] = pack_bf16x2(row[k], row[k + 1]);
    }
    for (int i = tid; i < 16 * 128; i += 256) {
        const int jj = i >> 7, ww = i & 127;
        const int kg = ww >> 3, sub = ww & 7;
        const int k = kg * 16 + (sub >> 2) * 8 + (sub & 3) * 2;
        const float* row = &WB[(size_t)((jj >> 2) * 256 + cbB + (jj & 3)) * 256];
        wsB[jj * 132 + ww] = pack_bf16x2(row[k], row[k + 1]);
    }
    __syncthreads();

    const bool isA = (w < 4);
    const int  wl  = isA ? w : w - 4;
    const uint* wsp = isA ? wsA : wsB;
    const int  wld = isA ? 260 : 132;
    float* gsp = isA ? gsA : gsB;
    const int  lw_u4 = isA ? 0 : lbB_u4;
    // per-warp gx fragment-load params
    const __nv_bfloat16* gxp = isA ? g_gx0b : gxBb;
    const int fourh = isA ? 2048 : 1024;
    const int hh    = isA ? 512 : 256;
    const int cbw   = isA ? cbA : cbB;

    const int b_e = tid & 127, top = tid >> 7;
    const int g = lane >> 2, c = lane & 3;
    const int gate0 = c >> 1;          // + nt*2
    const int cc0   = (c & 1) * 2;

    float creg[2][2] = {{0.f, 0.f}, {0.f, 0.f}};   // cell state in registers

    uint gxr[2][2][2];   // [m][nt][rowhalf], bf16x2 words
    auto load_gx = [&](int t) {
        #pragma unroll
        for (int m = 0; m < 2; m++)
            #pragma unroll
            for (int rh = 0; rh < 2; rh++) {
                const int row = wl * 32 + m * 16 + g + rh * 8;
                const size_t base = (size_t)(row * TSTEPS + t) * fourh + cbw + cc0;
                #pragma unroll
                for (int nt = 0; nt < 2; nt++)
                    gxr[m][nt][rh] = *(const uint*)&gxp[base + (nt * 2 + gate0) * hh];
            }
    };
    load_gx(0);

    for (int t = 0; t < TSTEPS; t++) {
        // ---- acc init from gx (bf16 -> fp32 via <<16) ----
        float acc[2][2][4];
        #pragma unroll
        for (int m = 0; m < 2; m++)
            #pragma unroll
            for (int nt = 0; nt < 2; nt++) {
                const uint w0 = gxr[m][nt][0], w1 = gxr[m][nt][1];
                acc[m][nt][0] = __uint_as_float(w0 << 16);
                acc[m][nt][1] = __uint_as_float(w0 & 0xffff0000u);
                acc[m][nt][2] = __uint_as_float(w1 << 16);
                acc[m][nt][3] = __uint_as_float(w1 & 0xffff0000u);
            }

        if (t > 0) {
            const uint4* hbp = (const uint4*)(g_hb[(t - 1) & 1]) + lw_u4;
            if (isA) rec_mma<32>(acc, hbp, (wl * 2 + 0) * 32, (wl * 2 + 1) * 32, lane, wsp, wld, g, c);
            else     rec_mma<16>(acc, hbp, (wl * 2 + 0) * 16, (wl * 2 + 1) * 16, lane, wsp, wld, g, c);
        }

        // ---- write gate preacts to gs (pure stores, fragment mapping) ----
        #pragma unroll
        for (int m = 0; m < 2; m++) {
            const int r0 = wl * 32 + m * 16 + g;
            #pragma unroll
            for (int nt = 0; nt < 2; nt++) {
                const int c0 = nt * 8 + c * 2;
                gsp[ c0      * 132 + r0    ] = acc[m][nt][0];
                gsp[(c0 + 1) * 132 + r0    ] = acc[m][nt][1];
                gsp[ c0      * 132 + r0 + 8] = acc[m][nt][2];
                gsp[(c0 + 1) * 132 + r0 + 8] = acc[m][nt][3];
            }
        }
        __syncthreads();

        // ---- cell update + paired bf16x2 h stores (c in registers) ----
        uint* hbw32 = (uint*)(g_hb[t & 1]);
        #pragma unroll
        for (int u = 0; u < 2; u++) {
            float* gs = u ? gsB : gsA;
            const int cb  = u ? cbB : cbA;
            const int lbE = u ? lbB_elem : 0;
            const int KGu = u ? 16 : 32;
            float hn2[2];
            #pragma unroll
            for (int cp = 0; cp < 2; cp++) {
                const int cc = top * 2 + cp;
                const float gi = gs[( 0 + cc) * 132 + b_e];
                const float gf = gs[( 4 + cc) * 132 + b_e];
                const float gg = gs[( 8 + cc) * 132 + b_e];
                const float go = gs[(12 + cc) * 132 + b_e];
                const float cold = creg[u][cp];
                const float cn = sigf(gf) * cold + sigf(gi) * tanhfast(gg);
                const float hn = sigf(go) * tanhfast(cn);
                creg[u][cp] = cn;
                hn2[cp] = hn;
                hstage[(u * 4 + cc) * 132 + b_e] = hn;
            }
            // one 4B store per unit: cells (top*2, top*2+1) are adjacent bf16 in
            // the fragment word (same lane_w, same reg, pos = cp; base even)
            const int col = cb + top * 2;
            const int kg = col >> 4, c16 = col & 15;
            const int blk = b_e >> 4, rl = b_e & 15;
            const int lane_w = (rl & 7) * 4 + ((c16 & 7) >> 1);
            const int reg = (rl >> 3) + 2 * (c16 >> 3);
            const int off = lbE + (blk * KGu + kg) * 256 + lane_w * 8 + reg * 2;
            hbw32[off >> 1] = pack_bf16x2(hn2[0], hn2[1]);
        }
        __syncthreads();   // hstage ready; all g_hb stores issued

        // ---- release barrier signal early (orders g_hb stores, CG pattern) ----
        if (t < TSTEPS - 1 && tid == 0) {
            asm volatile("st.release.gpu.u32 [%0], %1;"
                         :: "l"(g_flags + cta), "r"((unsigned)(t + 1)) : "memory");
        }

        // ---- prefetch next step's gx (barrier-independent) ----
        if (t + 1 < TSTEPS) load_gx(t + 1);

        // ---- coalesced float4 g_hcat write (not ordered by barrier; FC1-only) ----
        {
            const int uu = top;
            const int cb  = uu ? cbB : cbA;
            const int col = uu ? coloffB : 0;
            float4 hv;
            hv.x = hstage[(uu * 4 + 0) * 132 + b_e];
            hv.y = hstage[(uu * 4 + 1) * 132 + b_e];
            hv.z = hstage[(uu * 4 + 2) * 132 + b_e];
            hv.w = hstage[(uu * 4 + 3) * 132 + b_e];
            *(float4*)&g_hcat[((size_t)(b_e * TSTEPS + t)) * 1024 + col + cb] = hv;
        }

        // ---- acquire-poll across the 128 resident CTAs ----
        if (t < TSTEPS - 1) {
            if (tid < 128) {
                unsigned v;
                while (true) {
                    asm volatile("ld.acquire.gpu.u32 %0, [%1];"
                                 : "=r"(v) : "l"(g_flags + tid) : "memory");
                    if (v >= (unsigned)(t + 1)) break;
                    __nanosleep(8);
                }
            }
            __syncthreads();
        }
    }
}

// ------------------------------------------------------------------------------
// FC2 (7x256) + log_softmax, one warp per (b,t) row.
// ------------------------------------------------------------------------------
__global__ __launch_bounds__(256) void fc2_softmax(
    const float* __restrict__ W2, const float* __restrict__ b2,
    float* __restrict__ out)
{
    const int warp = threadIdx.x >> 5, lane = threadIdx.x & 31;
    const int row = blockIdx.x * 8 + warp;
    const float4* z4 = (const float4*)&g_z[(size_t)row * 256];
    const float4 z0 = z4[lane];
    const float4 z1 = z4[32 + lane];

    float logit[7];
    #pragma unroll
    for (int o = 0; o < 7; o++) {
        const float4* w4 = (const float4*)&W2[o * 256];
        const float4 w0 = w4[lane], w1 = w4[32 + lane];
        float p = z0.x * w0.x + z0.y * w0.y + z0.z * w0.z + z0.w * w0.w
                + z1.x * w1.x + z1.y * w1.y + z1.z * w1.z + z1.w * w1.w;
        #pragma unroll
        for (int s = 16; s > 0; s >>= 1) p += __shfl_xor_sync(0xffffffffu, p, s);
        logit[o] = p + b2[o];
    }
    float m = logit[0];
    #pragma unroll
    for (int o = 1; o < 7; o++) m = fmaxf(m, logit[o]);
    float se = 0.f;
    #pragma unroll
    for (int o = 0; o < 7; o++) se += expf(logit[o] - m);
    const float lse = logf(se);
    if (lane < 7) out[(size_t)row * 7 + lane] = logit[lane] - m - lse;
}

// ------------------------------------------------------------------------------
extern "C" void kernel_launch(void* const* d_in, const int* in_sizes, int n_in,
                              void* d_out, int out_size)
{
    const float* x0    = (const float*)d_in[0];
    const float* x1    = (const float*)d_in[1];
    const float* x2    = (const float*)d_in[2];
    const float* Wih0  = (const float*)d_in[3];
    const float* Whh0  = (const float*)d_in[4];
    const float* bih0  = (const float*)d_in[5];
    const float* bhh0  = (const float*)d_in[6];
    const float* Wih1  = (const float*)d_in[7];
    const float* Whh1  = (const float*)d_in[8];
    const float* bih1  = (const float*)d_in[9];
    const float* bhh1  = (const float*)d_in[10];
    const float* Wih2  = (const float*)d_in[11];
    const float* Whh2  = (const float*)d_in[12];
    const float* bih2  = (const float*)d_in[13];
    const float* bhh2  = (const float*)d_in[14];
    const float* fcW1  = (const float*)d_in[15];
    const float* fcb1  = (const float*)d_in[16];
    const float* fcW2  = (const float*)d_in[17];
    const float* fcb2  = (const float*)d_in[18];
    float* out = (float*)d_out;

    const int rec_smem = (16 * 260 + 16 * 132 + 2 * 16 * 132 + 8 * 132) * 4;
    cudaFuncSetAttribute(lstm_rec, cudaFuncAttributeMaxDynamicSharedMemorySize, rec_smem);

    reset_kernel<<<1, 128>>>();

    // input projections: gx = x @ W_ih^T + b_ih + b_hh   (bf16 mma, bf16 out)
    { dim3 g(2048 / 64, BT / 128); gemm_bf16<<<g, 256>>>(x0, -1, Wih0, bih0, bhh0, 0, BT, 2048, 300, 0); }
    { dim3 g(1024 / 64, BT / 128); gemm_bf16<<<g, 256>>>(x1, -1, Wih1, bih1, bhh1, 1, BT, 1024,  74, 0); }
    { dim3 g(1024 / 64, BT / 128); gemm_bf16<<<g, 256>>>(x2, -1, Wih2, bih2, bhh2, 2, BT, 1024,  35, 0); }

    // persistent recurrence over T=256 (bf16 tensor cores, 128 CTAs)
    lstm_rec<<<128, 256, rec_smem>>>(Whh0, Whh1, Whh2);

    // FC1 + ReLU: z = relu(hcat @ fc_W1^T + fc_b1)   (fp32 out)
    { dim3 g(256 / 64, BT / 128); gemm_bf16<<<g, 256>>>(nullptr, 0, fcW1, fcb1, nullptr, 3, BT, 256, 1024, 1); }

    // FC2 + log_softmax
    fc2_softmax<<<BT / 8, 256>>>(fcW2, fcb2, out);
}